// round 1
// baseline (speedup 1.0000x reference)
#include <cuda_runtime.h>
#include <math.h>

#define BB 8
#define SS 4096
#define DD 1024
#define NN 64
#define SHIFT 2048
#define NCH 32
#define CHL 128

#define TILE_T 32
#define DC 64
#define WPITCH 132
#define KC_ROWS 32
#define OWPITCH 66

// ---------------- scratch (device globals; no allocations allowed) ----------------
__device__ float g_wT[DD * 128];          // [d][o] interleaved: o=2n -> lw*kw, o=2n+1 -> lw*vw
__device__ float g_wsum[128];             // column sums of g_wT
__device__ float g_lbsum[128];            // sum_d lnb[d]*w[n][d]
__device__ float g_gate[DD];              // sigmoid(time_shift_gates)
__device__ float g_wkv[BB * SS * NN];
__device__ float g_states[BB * SS * NN];
__device__ float g_chunk[BB * NCH * NN];
__device__ float g_carry[BB * NCH * NN];

// ---------------- packed fp32x2 FMA (sm_103a FFMA2) ----------------
__device__ __forceinline__ float2 ffma2(float2 a, float2 b, float2 c) {
    float2 d;
    asm("fma.rn.f32x2 %0, %1, %2, %3;"
        : "=l"(*reinterpret_cast<unsigned long long*>(&d))
        : "l"(*reinterpret_cast<unsigned long long*>(&a)),
          "l"(*reinterpret_cast<unsigned long long*>(&b)),
          "l"(*reinterpret_cast<unsigned long long*>(&c)));
    return d;
}

// ---------------- prep kernels ----------------
__global__ void prep_a(const float* __restrict__ kw, const float* __restrict__ vw,
                       const float* __restrict__ lnw, const float* __restrict__ tsg) {
    int idx = blockIdx.x * 256 + threadIdx.x;   // 0..131071
    int d = idx >> 7;
    int o = idx & 127;
    int n = o >> 1;
    const float* src = (o & 1) ? vw : kw;
    g_wT[idx] = lnw[d] * src[n * DD + d];
    if (o == 0) g_gate[d] = 1.f / (1.f + expf(-tsg[d]));
}

__global__ void prep_b(const float* __restrict__ kw, const float* __restrict__ vw,
                       const float* __restrict__ lnb) {
    int o = threadIdx.x;                        // 128 threads
    int n = o >> 1;
    const float* src = (o & 1) ? vw : kw;
    float ws = 0.f, lb = 0.f;
    for (int d = 0; d < DD; d++) {
        ws += g_wT[d * 128 + o];
        lb += lnb[d] * src[n * DD + d];
    }
    g_wsum[o] = ws;
    g_lbsum[o] = lb;
}

// ---------------- kernel A: shift + LN(folded) + KV proj + wkv ----------------
// grid: BB * (SS/TILE_T) = 1024 blocks, 256 threads
// smem: xs[32*1024] | wsm[DC*WPITCH] | mu[32] | inv[32]
__global__ void __launch_bounds__(256, 1)
kernelA(const float* __restrict__ x, const float* __restrict__ tf) {
    extern __shared__ float sm[];
    float* xs_s = sm;
    float* wsm = sm + TILE_T * DD;
    float* mu_s = wsm + DC * WPITCH;
    float* inv_s = mu_s + TILE_T;

    int b = blockIdx.x >> 7;                 // / (SS/TILE_T) = /128
    int t0 = (blockIdx.x & 127) * TILE_T;
    int tid = threadIdx.x;
    int lane = tid & 31;
    int warp = tid >> 5;

    // ---- token shift + stats; store blended row ----
    for (int i = 0; i < 4; i++) {
        int r = warp * 4 + i;
        int t = t0 + r;
        int tc = t ^ SHIFT;                  // (t + S/2) mod S
        const float* xt = x + ((size_t)(b * SS + t)) * DD;
        const float* xc = x + ((size_t)(b * SS + tc)) * DD;
        float vals[32];
        float sum = 0.f, sq = 0.f;
#pragma unroll
        for (int j = 0; j < 32; j++) {
            int d = j * 32 + lane;
            float gx = g_gate[d];
            float xv = xt[d];
            float xsv = xv + gx * (xc[d] - xv);
            vals[j] = xsv;
            sum += xsv;
            sq += xsv * xsv;
        }
#pragma unroll
        for (int off = 16; off; off >>= 1) {
            sum += __shfl_xor_sync(0xffffffffu, sum, off);
            sq  += __shfl_xor_sync(0xffffffffu, sq, off);
        }
        float mu = sum * (1.f / DD);
        float var = sq * (1.f / DD) - mu * mu;
        float inv = rsqrtf(var + 1e-5f);
        if (lane == 0) { mu_s[r] = mu; inv_s[r] = inv; }
#pragma unroll
        for (int j = 0; j < 32; j++)
            xs_s[r * DD + j * 32 + lane] = vals[j];
    }

    // ---- GEMM: (32 rows x 1024) @ wT(1024 x 128), f32x2 pairs (k_n, v_n) ----
    int og = lane;                            // out-group: outs 4*og .. 4*og+3
    int r0 = warp * 4;                        // 4 rows per warp
    float2 acc[4][2];
#pragma unroll
    for (int i = 0; i < 4; i++) { acc[i][0] = make_float2(0.f, 0.f); acc[i][1] = make_float2(0.f, 0.f); }

    for (int ch = 0; ch < DD / DC; ch++) {
        __syncthreads();
        // stage weight chunk [DC][128] -> wsm pitch WPITCH
#pragma unroll
        for (int q = 0; q < 8; q++) {
            int e = q * 256 + tid;            // float4 index 0..2047
            int dl = e >> 5;
            int oo = (e & 31) << 2;
            float4 wv = *reinterpret_cast<const float4*>(&g_wT[(ch * DC + dl) * 128 + oo]);
            *reinterpret_cast<float4*>(&wsm[dl * WPITCH + oo]) = wv;
        }
        __syncthreads();
#pragma unroll 8
        for (int dl = 0; dl < DC; dl++) {
            int d = ch * DC + dl;
            float a0 = xs_s[(r0 + 0) * DD + d];
            float a1 = xs_s[(r0 + 1) * DD + d];
            float a2 = xs_s[(r0 + 2) * DD + d];
            float a3 = xs_s[(r0 + 3) * DD + d];
            float2 w0 = *reinterpret_cast<const float2*>(&wsm[dl * WPITCH + og * 4]);
            float2 w1 = *reinterpret_cast<const float2*>(&wsm[dl * WPITCH + og * 4 + 2]);
            float2 av;
            av = make_float2(a0, a0);
            acc[0][0] = ffma2(av, w0, acc[0][0]); acc[0][1] = ffma2(av, w1, acc[0][1]);
            av = make_float2(a1, a1);
            acc[1][0] = ffma2(av, w0, acc[1][0]); acc[1][1] = ffma2(av, w1, acc[1][1]);
            av = make_float2(a2, a2);
            acc[2][0] = ffma2(av, w0, acc[2][0]); acc[2][1] = ffma2(av, w1, acc[2][1]);
            av = make_float2(a3, a3);
            acc[3][0] = ffma2(av, w0, acc[3][0]); acc[3][1] = ffma2(av, w1, acc[3][1]);
        }
    }

    // ---- epilogue: finish LN fold, apply wkv nonlinearity ----
#pragma unroll
    for (int i = 0; i < 4; i++) {
        int r = r0 + i;
        int t = t0 + r;
        float mu = mu_s[r];
        float inv = inv_s[r];
#pragma unroll
        for (int p = 0; p < 2; p++) {
            int n = og * 2 + p;
            float kk = inv * (acc[i][p].x - mu * g_wsum[2 * n])     + g_lbsum[2 * n];
            float vv = inv * (acc[i][p].y - mu * g_wsum[2 * n + 1]) + g_lbsum[2 * n + 1];
            float wkv = expf(-expf(tf[n]) * kk) * vv;
            g_wkv[((size_t)(b * SS + t)) * NN + n] = wkv;
        }
    }
}

// ---------------- scan kernels (chunked linear recurrence) ----------------
__global__ void scan_chunks(const float* __restrict__ td) {
    int g = blockIdx.x * blockDim.x + threadIdx.x;  // 16384 threads
    int n = g & (NN - 1);
    int c = (g >> 6) & (NCH - 1);
    int b = g >> 11;
    float w = expf(td[n]);
    const float* p = g_wkv + ((size_t)(b * SS + c * CHL)) * NN + n;
    float acc = 0.f;
#pragma unroll 8
    for (int i = 0; i < CHL; i++)
        acc = acc * w + p[i * NN];
    g_chunk[(b * NCH + c) * NN + n] = acc;
}

__global__ void scan_carry(const float* __restrict__ td, float* __restrict__ lastout,
                           int write_last) {
    int tid = threadIdx.x;                   // 512 threads
    int n = tid & (NN - 1);
    int b = tid >> 6;
    float wL = expf((float)CHL * td[n]);
    float carry = 0.f;
    for (int c = 0; c < NCH; c++) {
        g_carry[(b * NCH + c) * NN + n] = carry;
        carry = carry * wL + g_chunk[(b * NCH + c) * NN + n];
    }
    if (write_last) lastout[b * NN + n] = carry;
}

__global__ void scan_expand(const float* __restrict__ td) {
    int g = blockIdx.x * blockDim.x + threadIdx.x;
    int n = g & (NN - 1);
    int c = (g >> 6) & (NCH - 1);
    int b = g >> 11;
    float w = expf(td[n]);
    float st = g_carry[(b * NCH + c) * NN + n];
    const float* p = g_wkv + ((size_t)(b * SS + c * CHL)) * NN + n;
    float* q = g_states + ((size_t)(b * SS + c * CHL)) * NN + n;
#pragma unroll 8
    for (int i = 0; i < CHL; i++) {
        st = st * w + p[i * NN];
        q[i * NN] = st;
    }
}

// ---------------- kernel C: output projection (32768 x 64) @ (64 x 1024) ----------------
// grid: BB*(SS/KC_ROWS)*2 = 2048 blocks, 256 threads
// smem: ow_sm[512*OWPITCH] | s_sm[32*64]
__global__ void __launch_bounds__(256, 1)
kernelC(const float* __restrict__ ow, float* __restrict__ out) {
    extern __shared__ float sm[];
    float* ow_sm = sm;
    float* s_sm = sm + 512 * OWPITCH;

    int half = blockIdx.x & 1;
    int rowblk = blockIdx.x >> 1;            // 0..1023
    int b = rowblk >> 7;
    int t0 = (rowblk & 127) * KC_ROWS;
    int tid = threadIdx.x;

    // stage ow half [512][64] -> pitch OWPITCH (conflict-free LDS.64)
#pragma unroll
    for (int q = 0; q < 32; q++) {
        int e = q * 256 + tid;               // float4 idx 0..8191
        int dl = e >> 4;
        int nn4 = (e & 15) << 2;
        float4 wv = *reinterpret_cast<const float4*>(&ow[(size_t)(half * 512 + dl) * NN + nn4]);
        float* dst = &ow_sm[dl * OWPITCH + nn4];
        *reinterpret_cast<float2*>(dst) = make_float2(wv.x, wv.y);
        *reinterpret_cast<float2*>(dst + 2) = make_float2(wv.z, wv.w);
    }
    // stage states [32][64]
#pragma unroll
    for (int q = 0; q < 2; q++) {
        int e = q * 256 + tid;               // float4 idx 0..511
        *reinterpret_cast<float4*>(&s_sm[e * 4]) =
            *reinterpret_cast<const float4*>(&g_states[((size_t)(b * SS + t0)) * NN + e * 4]);
    }
    __syncthreads();

    float* outbase = out + ((size_t)(b * SS + t0)) * DD + half * 512;
    for (int dsel = 0; dsel < 2; dsel++) {
        int dl = dsel * 256 + tid;
        float2 wreg[32];
#pragma unroll
        for (int j = 0; j < 32; j++)
            wreg[j] = *reinterpret_cast<const float2*>(&ow_sm[dl * OWPITCH + 2 * j]);
        for (int r = 0; r < KC_ROWS; r += 2) {
            float2 a0 = make_float2(0.f, 0.f);
            float2 a1 = make_float2(0.f, 0.f);
#pragma unroll
            for (int j = 0; j < 32; j++) {
                float2 s0 = *reinterpret_cast<const float2*>(&s_sm[r * NN + 2 * j]);
                float2 s1 = *reinterpret_cast<const float2*>(&s_sm[(r + 1) * NN + 2 * j]);
                a0 = ffma2(s0, wreg[j], a0);
                a1 = ffma2(s1, wreg[j], a1);
            }
            outbase[(size_t)r * DD + dl] = a0.x + a0.y;
            outbase[(size_t)(r + 1) * DD + dl] = a1.x + a1.y;
        }
    }
}

// ---------------- launch ----------------
extern "C" void kernel_launch(void* const* d_in, const int* in_sizes, int n_in,
                              void* d_out, int out_size) {
    const float* x   = (const float*)d_in[0];
    const float* td  = (const float*)d_in[1];
    const float* tf  = (const float*)d_in[2];
    const float* kw  = (const float*)d_in[3];
    const float* vw  = (const float*)d_in[4];
    const float* ow  = (const float*)d_in[5];
    const float* tsg = (const float*)d_in[6];
    const float* lnw = (const float*)d_in[7];
    const float* lnb = (const float*)d_in[8];
    float* out = (float*)d_out;

    const int SMEM_A = (TILE_T * DD + DC * WPITCH + 2 * TILE_T) * (int)sizeof(float);
    const int SMEM_C = (512 * OWPITCH + KC_ROWS * NN) * (int)sizeof(float);
    cudaFuncSetAttribute(kernelA, cudaFuncAttributeMaxDynamicSharedMemorySize, SMEM_A);
    cudaFuncSetAttribute(kernelC, cudaFuncAttributeMaxDynamicSharedMemorySize, SMEM_C);

    prep_a<<<(DD * 128) / 256, 256>>>(kw, vw, lnw, tsg);
    prep_b<<<1, 128>>>(kw, vw, lnb);
    kernelA<<<BB * (SS / TILE_T), 256, SMEM_A>>>(x, tf);
    scan_chunks<<<(BB * NCH * NN) / 256, 256>>>(td);
    int write_last = (out_size >= BB * SS * DD + BB * NN) ? 1 : 0;
    scan_carry<<<1, 512>>>(td, out + (size_t)BB * SS * DD, write_last);
    scan_expand<<<(BB * NCH * NN) / 256, 256>>>(td);
    kernelC<<<BB * (SS / KC_ROWS) * 2, 256, SMEM_C>>>(ow, out);
}